// round 14
// baseline (speedup 1.0000x reference)
#include <cuda_runtime.h>
#include <cuda_fp16.h>
#include <cstdint>
#include <cstddef>

#define HH 1024
#define DD 256
#define BSz 1024
#define TS 256
#define K0T 1280
#define K1T 2048
#define GSK 148

typedef __half h16;

// ---------------- persistent device scratch ----------------
__device__ __align__(256) h16   g_W0[3ull * HH * K0T];
__device__ __align__(256) h16   g_W1[3ull * HH * K1T];
__device__ __align__(256) h16   g_Wfc[(size_t)DD * HH];
__device__ __align__(256) float g_C0[(size_t)BSz * 3 * HH];
__device__ __align__(256) float g_base1[3 * HH];
__device__ __align__(256) float g_h0[(size_t)BSz * HH];
__device__ __align__(256) float g_h1[(size_t)BSz * HH];
__device__ __align__(256) h16   g_A0[2][(size_t)BSz * K0T];
__device__ __align__(256) h16   g_A1[2][(size_t)BSz * K1T];
__device__ __align__(256) float g_part[(size_t)GSK * 256 * 128];
__device__ int g_flag[GSK];

// ---------------- helpers ----------------
__device__ __forceinline__ uint32_t smem_u32(const void* p) {
    return (uint32_t)__cvta_generic_to_shared(p);
}
__device__ __forceinline__ void cpa16(uint32_t d, const void* s) {
    asm volatile("cp.async.cg.shared.global [%0],[%1],16;" :: "r"(d), "l"(s));
}
#define CP_COMMIT() asm volatile("cp.async.commit_group;")
#define CP_WAIT1()  asm volatile("cp.async.wait_group 1;")
#define CP_WAIT0()  asm volatile("cp.async.wait_group 0;")

__device__ __forceinline__ void ldm4(uint32_t (&r)[4], uint32_t a) {
    asm volatile("ldmatrix.sync.aligned.m8n8.x4.shared.b16 {%0,%1,%2,%3},[%4];"
                 : "=r"(r[0]), "=r"(r[1]), "=r"(r[2]), "=r"(r[3]) : "r"(a));
}
__device__ __forceinline__ void ldm2(uint32_t (&r)[2], uint32_t a) {
    asm volatile("ldmatrix.sync.aligned.m8n8.x2.shared.b16 {%0,%1},[%2];"
                 : "=r"(r[0]), "=r"(r[1]) : "r"(a));
}
__device__ __forceinline__ void mma16(float (&c)[4], const uint32_t (&a)[4], uint32_t b0, uint32_t b1) {
    asm volatile("mma.sync.aligned.m16n8k16.row.col.f32.f16.f16.f32 "
                 "{%0,%1,%2,%3},{%4,%5,%6,%7},{%8,%9},{%0,%1,%2,%3};"
                 : "+f"(c[0]), "+f"(c[1]), "+f"(c[2]), "+f"(c[3])
                 : "r"(a[0]), "r"(a[1]), "r"(a[2]), "r"(a[3]), "r"(b0), "r"(b1));
}
__device__ __forceinline__ float fsigm(float x) { return __fdividef(1.f, 1.f + __expf(-x)); }

__device__ __forceinline__ uint32_t swz(int row, int sub) {
    return (uint32_t)(row * 128 + ((sub ^ (row & 7)) * 16));
}

// ---------------- GRU GEMM stage: K=64 chunk, warp tile 32x32 per gate ----------------
__device__ __forceinline__ void hstage(uint32_t st, float (&aR)[2][4][4], float (&aZ)[2][4][4],
                                       float (&aN)[2][4][4], int wm, int wn, int lane) {
#pragma unroll
    for (int kk = 0; kk < 4; kk++) {
        uint32_t af[2][4];
#pragma unroll
        for (int i = 0; i < 2; i++) {
            int r = wm * 32 + i * 16 + (lane & 15);
            ldm4(af[i], st + swz(r, 2 * kk + (lane >> 4)));
        }
        int nrow = wn * 32 + ((lane & 16) >> 1) + (lane & 7);
        int bch = 2 * kk + ((lane >> 3) & 1);
#pragma unroll
        for (int g = 0; g < 3; g++) {
            uint32_t sb = st + 16384 + g * 8192;
            float (&ac)[2][4][4] = (g == 0) ? aR : ((g == 1) ? aZ : aN);
#pragma unroll
            for (int j = 0; j < 2; j++) {
                uint32_t bf[4];
                ldm4(bf, sb + swz(nrow + j * 16, bch));
                mma16(ac[0][2 * j],     af[0], bf[0], bf[1]);
                mma16(ac[0][2 * j + 1], af[0], bf[2], bf[3]);
                mma16(ac[1][2 * j],     af[1], bf[0], bf[1]);
                mma16(ac[1][2 * j + 1], af[1], bf[2], bf[3]);
            }
        }
    }
}

// L2-direct accumulator <-> gmem helpers (compile-time indices only)
#define ACC_STORE(A, base) do { \
    _Pragma("unroll") for (int i_ = 0; i_ < 2; i_++) \
    _Pragma("unroll") for (int j_ = 0; j_ < 4; j_++) \
    _Pragma("unroll") for (int k_ = 0; k_ < 4; k_++) \
        __stcg(dst + (base) + i_ * 16 + j_ * 4 + k_, A[i_][j_][k_]); \
} while (0)
#define ACC_MERGE(A, base) do { \
    _Pragma("unroll") for (int i_ = 0; i_ < 2; i_++) \
    _Pragma("unroll") for (int j_ = 0; j_ < 4; j_++) \
    _Pragma("unroll") for (int k_ = 0; k_ < 4; k_++) \
        A[i_][j_][k_] += __ldcg(src + (base) + i_ * 16 + j_ * 4 + k_); \
} while (0)

// ---------------- Stream-K fused GRU layer kernel: 148 CTAs ----------------
// KT=1280 -> layer0 (A=[x|h0], per-row C0), KXCH=4. KT=2048 -> layer1, KXCH=16.
template <int KT, int KXCH>
__global__ void __launch_bounds__(256, 1) gru_sk(int t, const float* __restrict__ vghn) {
    constexpr int NCH = KT / 64;
    constexpr int TOTAL = 128 * NCH;
    constexpr int BASE = TOTAL / GSK;
    constexpr int REM = TOTAL - BASE * GSK;
    constexpr int STAGE = 40960;
    extern __shared__ char dsm[];
    const int tid = threadIdx.x, lane = tid & 31, warp = tid >> 5;
    const int wm = warp >> 1, wn = warp & 1;
    const int b = blockIdx.x;
    const uint32_t sbase = smem_u32(dsm);
    const int nt = (t + 1) & 1;

    const h16* Abase;
    const h16* Wb;
    if (KT == K0T) { Abase = g_A0[t & 1]; Wb = g_W0; }
    else           { Abase = g_A1[t & 1]; Wb = g_W1; }

    const int q0 = b * BASE + min(b, REM);
    const int cnt = BASE + (b < REM ? 1 : 0);
    const int q1 = q0 + cnt;
    const int tA = q0 / NCH;
    const int te = (tA + 1) * NCH;
    const bool two = (q1 > te);

#pragma unroll 1
    for (int fi = 0; fi < (two ? 2 : 1); fi++) {
        int fs, fe;
        if (two && fi == 0) { fs = te; fe = q1; }          // later-tile partial FIRST
        else                { fs = q0; fe = min(q1, te); }
        const int tile = fs / NCH;
        const int m0 = (tile >> 4) * 128, n0 = (tile & 15) * 64;
        const int cs = fs - tile * NCH, ce = fe - tile * NCH;

        auto load_chunk = [&](int c) {
            uint32_t st = sbase + (c % 3) * STAGE;
            int kb = c * 64;
#pragma unroll
            for (int l = 0; l < 10; l++) {
                int q = tid + l * 256;
                if (q < 1024) {
                    int row = q >> 3, sub = q & 7;
                    cpa16(st + swz(row, sub), Abase + (size_t)(m0 + row) * KT + kb + sub * 8);
                } else {
                    int q2 = q - 1024;
                    int gate = q2 >> 9, r2 = q2 & 511;
                    int row = r2 >> 3, sub = r2 & 7;
                    cpa16(st + 16384 + gate * 8192 + swz(row, sub),
                          Wb + (size_t)gate * HH * KT + (size_t)(n0 + row) * KT + kb + sub * 8);
                }
            }
            CP_COMMIT();
        };

        float aR[2][4][4] = {}, aZ[2][4][4] = {}, aNi[2][4][4] = {}, aNh[2][4][4] = {};

        load_chunk(cs);
        if (cs + 1 < ce) load_chunk(cs + 1);
#pragma unroll 1
        for (int c = cs; c < ce; c++) {
            if (c + 1 < ce) { CP_WAIT1(); } else { CP_WAIT0(); }
            __syncthreads();                 // all warps done with buffer (c+2)%3's previous user
            if (c + 2 < ce) load_chunk(c + 2);
            uint32_t st = sbase + (c % 3) * STAGE;
            if (c < KXCH) hstage(st, aR, aZ, aNi, wm, wn, lane);
            else          hstage(st, aR, aZ, aNh, wm, wn, lane);
        }
        __syncthreads();

        if (ce == NCH) {
            // ---- owner: merge predecessors covering chunks [0, cs) ----
            int need = cs;
            int pb = b - 1;
            const int tileq = tile * NCH;
            while (need > 0) {
                int pq0 = pb * BASE + min(pb, REM);
                int pq1 = pq0 + BASE + (pb < REM ? 1 : 0);
                int m = pq1 - max(pq0, tileq);
                if (tid == 0) { while (atomicAdd(&g_flag[pb], 0) == 0) {} }
                __syncthreads();
                __threadfence();
                const float* src = g_part + ((size_t)pb * 256 + tid) * 128;
                ACC_MERGE(aR, 0);
                ACC_MERGE(aZ, 32);
                ACC_MERGE(aNi, 64);
                ACC_MERGE(aNh, 96);
                __syncthreads();
                if (tid == 0) atomicExch(&g_flag[pb], 0);
                need -= m;
                pb--;
            }
            // ---- epilogue ----
            const int g4 = lane >> 2, t4 = lane & 3;
            float* hs = (KT == K0T) ? g_h0 : g_h1;
#pragma unroll
            for (int i = 0; i < 2; i++) {
                int rb = m0 + wm * 32 + i * 16 + g4;
#pragma unroll
                for (int j = 0; j < 4; j++) {
                    int cc = n0 + wn * 32 + j * 8 + 2 * t4;
                    float2 v1r = {0.f, 0.f}, v1z = {0.f, 0.f}, v1n = {0.f, 0.f};
                    if (KT == K1T) {
                        v1r = *(const float2*)(g_base1 + cc);
                        v1z = *(const float2*)(g_base1 + HH + cc);
                        v1n = *(const float2*)(g_base1 + 2 * HH + cc);
                    }
                    float2 vg = *(const float2*)(vghn + cc);
#pragma unroll
                    for (int hf = 0; hf < 2; hf++) {
                        int r = rb + hf * 8;
                        float2 cm_r = v1r, cm_z = v1z, cm_n = v1n;
                        if (KT == K0T) {
                            const float* cp = g_C0 + (size_t)r * 3072 + cc;
                            cm_r = *(const float2*)cp;
                            cm_z = *(const float2*)(cp + HH);
                            cm_n = *(const float2*)(cp + 2 * HH);
                        }
                        float2 hp = *(const float2*)(hs + (size_t)r * HH + cc);
                        float h[2];
#pragma unroll
                        for (int e = 0; e < 2; e++) {
                            float pr  = aR[i][j][hf * 2 + e]  + (e ? cm_r.y : cm_r.x);
                            float pz  = aZ[i][j][hf * 2 + e]  + (e ? cm_z.y : cm_z.x);
                            float gin = aNi[i][j][hf * 2 + e] + (e ? cm_n.y : cm_n.x);
                            float ghn = aNh[i][j][hf * 2 + e] + (e ? vg.y : vg.x);
                            float rr = fsigm(pr);
                            float zz = fsigm(pz);
                            float nn = tanhf(gin + rr * ghn);
                            float hv = e ? hp.y : hp.x;
                            h[e] = (1.f - zz) * nn + zz * hv;
                        }
                        *(float2*)(hs + (size_t)r * HH + cc) = make_float2(h[0], h[1]);
                        __half2 hh = __floats2half2_rn(h[0], h[1]);
                        if (KT == K0T) {
                            *(__half2*)(g_A1[t & 1] + (size_t)r * K1T + cc) = hh;
                            *(__half2*)(g_A0[nt] + (size_t)r * K0T + DD + cc) = hh;
                        } else {
                            *(__half2*)(g_A1[nt] + (size_t)r * K1T + HH + cc) = hh;
                        }
                    }
                }
            }
        } else {
            // ---- non-owner: publish partial (L2-direct) ----
            float* dst = g_part + ((size_t)b * 256 + tid) * 128;
            ACC_STORE(aR, 0);
            ACC_STORE(aZ, 32);
            ACC_STORE(aNi, 64);
            ACC_STORE(aNh, 96);
            __threadfence();
            __syncthreads();
            if (tid == 0) atomicExch(&g_flag[b], 1);
        }
    }
}

// ---------------- FC + activation + feedback (fp16 in, fp32 accum, BM=64 BN=32) ----------------
__global__ void __launch_bounds__(256, 1) fc_hmma(int t, const float* __restrict__ bfc, float* __restrict__ out) {
    constexpr int STAGE = 12288;
    extern __shared__ char dsm[];
    const int tid = threadIdx.x, lane = tid & 31, warp = tid >> 5;
    const int wm = warp >> 2, wn = warp & 3;
    const int m0 = blockIdx.y * 64, n0 = blockIdx.x * 32;
    const int nt = (t + 1) & 1;
    const uint32_t sbase = smem_u32(dsm);
    const h16* A = g_A1[nt];  // h1n at col offset HH

    auto load_chunk = [&](int c) {
        uint32_t st = sbase + (c % 3) * STAGE;
        int kb = c * 64;
#pragma unroll
        for (int l = 0; l < 3; l++) {
            int q = tid + l * 256;
            if (q < 512) {
                int row = q >> 3, sub = q & 7;
                cpa16(st + swz(row, sub), A + (size_t)(m0 + row) * K1T + HH + kb + sub * 8);
            } else {
                int q2 = q - 512;
                int row = q2 >> 3, sub = q2 & 7;
                cpa16(st + 8192 + swz(row, sub), g_Wfc + (size_t)(n0 + row) * HH + kb + sub * 8);
            }
        }
        CP_COMMIT();
    };

    float acc[2][4] = {};

    load_chunk(0);
    load_chunk(1);
#pragma unroll 1
    for (int c = 0; c < 16; c++) {
        if (c + 1 < 16) { CP_WAIT1(); } else { CP_WAIT0(); }
        __syncthreads();
        if (c + 2 < 16) load_chunk(c + 2);
        uint32_t st = sbase + (c % 3) * STAGE;
#pragma unroll
        for (int kk = 0; kk < 4; kk++) {
            uint32_t af[2][4];
#pragma unroll
            for (int i = 0; i < 2; i++) {
                int r = wm * 32 + i * 16 + (lane & 15);
                ldm4(af[i], st + swz(r, 2 * kk + (lane >> 4)));
            }
            int nrow = wn * 8 + (lane & 7);
            int bch = 2 * kk + ((lane >> 3) & 1);
            uint32_t bf[2];
            ldm2(bf, st + 8192 + swz(nrow, bch));
            mma16(acc[0], af[0], bf[0], bf[1]);
            mma16(acc[1], af[1], bf[0], bf[1]);
        }
    }
    __syncthreads();

    float* fsm = (float*)dsm;
    const int g4 = lane >> 2, t4 = lane & 3;
#pragma unroll
    for (int i = 0; i < 2; i++)
#pragma unroll
        for (int hf = 0; hf < 2; hf++) {
            int r = wm * 32 + i * 16 + g4 + hf * 8;
            int cl = wn * 8 + 2 * t4;
            fsm[r * 34 + cl]     = acc[i][hf * 2]     + bfc[n0 + cl];
            fsm[r * 34 + cl + 1] = acc[i][hf * 2 + 1] + bfc[n0 + cl + 1];
        }
    __syncthreads();

    const int bx = blockIdx.x;
    if (bx == 0) {
        if (tid < 64) {
            int b = m0 + tid;
            float* row = fsm + tid * 34;
            float* op = out + (size_t)b * (TS * DD) + (size_t)t * DD;
            h16* xp = g_A0[nt] + (size_t)b * K0T;
            float mx = row[0];
            for (int c = 1; c < 32; c++) mx = fmaxf(mx, row[c]);
            float sum = 0.f;
            for (int c = 0; c < 32; c++) { float e = __expf(row[c] - mx); row[c] = e; sum += e; }
            float inv = __fdividef(1.f, sum);
            for (int c = 0; c < 32; c++) { float v = row[c] * inv; op[c] = v; xp[c] = __float2half_rn(v); }
        }
    } else if (bx == 1) {
        if (tid < 64) {
            int b = m0 + tid;
            float* row = fsm + tid * 34;
            float* op = out + (size_t)b * (TS * DD) + (size_t)t * DD + 32;
            h16* xp = g_A0[nt] + (size_t)b * K0T + 32;
            float mx = row[0];
            for (int c = 1; c < 15; c++) mx = fmaxf(mx, row[c]);
            float sum = 0.f;
            for (int c = 0; c < 15; c++) { float e = __expf(row[c] - mx); row[c] = e; sum += e; }
            float inv = __fdividef(1.f, sum);
            for (int c = 0; c < 15; c++) { float v = row[c] * inv; op[c] = v; xp[c] = __float2half_rn(v); }
            for (int c = 15; c < 32; c++) { float v = fsigm(row[c]); op[c] = v; xp[c] = __float2half_rn(v); }
        }
    } else {
        for (int idx = tid; idx < 2048; idx += 256) {
            int r = idx >> 5, cl = idx & 31;
            int b = m0 + r, c = n0 + cl;
            float v = fsigm(fsm[r * 34 + cl]);
            out[(size_t)b * (TS * DD) + (size_t)t * DD + c] = v;
            g_A0[nt][(size_t)b * K0T + c] = __float2half_rn(v);
        }
    }
}

// ---------------- C0 = glob @ W_ih0[:, :H].T + biases (fp32, once per replay) ----------------
__global__ void __launch_bounds__(256) c0_kernel(const float* __restrict__ emb, const float* __restrict__ Wih0,
                                                 const float* __restrict__ bih0, const float* __restrict__ bhh0) {
    __shared__ float As[16][64], Bs[16][64];
    int tid = threadIdx.x;
    int tx = tid & 15, ty = tid >> 4;
    int m0 = blockIdx.y * 64, n0 = blockIdx.x * 64;
    float acc[4][4] = {};
    for (int k0 = 0; k0 < HH; k0 += 16) {
#pragma unroll
        for (int l = 0; l < 4; l++) {
            int e = tid + l * 256;
            int rr = e >> 4, kk = e & 15;
            As[kk][rr] = emb[(size_t)(m0 + rr) * 3072 + k0 + kk];
            Bs[kk][rr] = Wih0[(size_t)(n0 + rr) * K0T + k0 + kk];
        }
        __syncthreads();
#pragma unroll
        for (int kk = 0; kk < 16; kk++) {
            float av[4], bv[4];
#pragma unroll
            for (int i = 0; i < 4; i++) av[i] = As[kk][ty * 4 + i];
#pragma unroll
            for (int j = 0; j < 4; j++) bv[j] = Bs[kk][tx * 4 + j];
#pragma unroll
            for (int i = 0; i < 4; i++)
#pragma unroll
                for (int j = 0; j < 4; j++) acc[i][j] += av[i] * bv[j];
        }
        __syncthreads();
    }
#pragma unroll
    for (int i = 0; i < 4; i++)
#pragma unroll
        for (int j = 0; j < 4; j++) {
            int r = m0 + ty * 4 + i, c = n0 + tx * 4 + j;
            g_C0[(size_t)r * 3072 + c] = acc[i][j] + bih0[c] + (c < 2 * HH ? bhh0[c] : 0.f);
        }
}

// ---------------- combined setup kernel ----------------
__global__ void setup_all(const float* __restrict__ Wih0, const float* __restrict__ Whh0,
                          const float* __restrict__ Wih1, const float* __restrict__ Whh1,
                          const float* __restrict__ Wfc,  const float* __restrict__ bih1,
                          const float* __restrict__ bhh1, const float* __restrict__ emb,
                          const float* __restrict__ dyn) {
    const int stride = gridDim.x * blockDim.x;
    const int t0 = blockIdx.x * blockDim.x + threadIdx.x;
    for (int idx = t0; idx < 3 * HH * K0T; idx += stride) {
        int gr = idx / K0T, k = idx - gr * K0T;
        float v = (k < DD) ? Wih0[(size_t)gr * K0T + HH + k] : Whh0[(size_t)gr * HH + (k - DD)];
        g_W0[idx] = __float2half_rn(v);
    }
    for (int idx = t0; idx < 3 * HH * K1T; idx += stride) {
        int gr = idx / K1T, k = idx - gr * K1T;
        float v = (k < HH) ? Wih1[(size_t)gr * HH + k] : Whh1[(size_t)gr * HH + (k - HH)];
        g_W1[idx] = __float2half_rn(v);
    }
    for (int i = t0; i < DD * HH; i += stride) {
        g_Wfc[i] = __float2half_rn(Wfc[i]);
        if (i < 3 * HH) g_base1[i] = bih1[i] + (i < 2 * HH ? bhh1[i] : 0.f);
    }
    for (int i = t0; i < BSz * HH; i += stride) {
        int b = i >> 10, n = i & 1023;
        float h0 = emb[(size_t)b * 3072 + HH + n];
        float h1 = emb[(size_t)b * 3072 + 2 * HH + n];
        g_h0[i] = h0;
        g_h1[i] = h1;
        g_A0[0][(size_t)b * K0T + DD + n] = __float2half_rn(h0);
        g_A1[0][(size_t)b * K1T + HH + n] = __float2half_rn(h1);
        if (n < DD) g_A0[0][(size_t)b * K0T + n] = __float2half_rn(dyn[(size_t)b * TS * DD + n]);
    }
    if (t0 < GSK) g_flag[t0] = 0;
}

// ---------------- host ----------------
extern "C" void kernel_launch(void* const* d_in, const int* in_sizes, int n_in,
                              void* d_out, int out_size) {
    const float* emb  = (const float*)d_in[0];
    const float* dyn  = (const float*)d_in[1];
    const float* Wih0 = (const float*)d_in[3];
    const float* Whh0 = (const float*)d_in[4];
    const float* bih0 = (const float*)d_in[5];
    const float* bhh0 = (const float*)d_in[6];
    const float* Wih1 = (const float*)d_in[7];
    const float* Whh1 = (const float*)d_in[8];
    const float* bih1 = (const float*)d_in[9];
    const float* bhh1 = (const float*)d_in[10];
    const float* Wfc  = (const float*)d_in[11];
    const float* bfc  = (const float*)d_in[12];
    float* out = (float*)d_out;

    const int SM = 3 * 40960;  // 122880 bytes dynamic smem -> forces 1 CTA/SM
    cudaFuncSetAttribute((const void*)gru_sk<K0T, 4>,  cudaFuncAttributeMaxDynamicSharedMemorySize, SM);
    cudaFuncSetAttribute((const void*)gru_sk<K1T, 16>, cudaFuncAttributeMaxDynamicSharedMemorySize, SM);
    const int SMF = 3 * 12288;
    cudaFuncSetAttribute((const void*)fc_hmma, cudaFuncAttributeMaxDynamicSharedMemorySize, SMF);

    setup_all<<<2048, 256>>>(Wih0, Whh0, Wih1, Whh1, Wfc, bih1, bhh1, emb, dyn);
    c0_kernel<<<dim3(48, 16), 256>>>(emb, Wih0, bih0, bhh0);

    for (int t = 0; t < TS; t++) {
        gru_sk<K0T, 4><<<GSK, 256, SM>>>(t, bhh0 + 2 * HH);
        gru_sk<K1T, 16><<<GSK, 256, SM>>>(t, bhh1 + 2 * HH);
        fc_hmma<<<dim3(8, 16), 256, SMF>>>(t, bfc, out);
    }
}

// round 15
// speedup vs baseline: 1.7720x; 1.7720x over previous
#include <cuda_runtime.h>
#include <cuda_fp16.h>
#include <cstdint>
#include <cstddef>

#define HH 1024
#define DD 256
#define BSz 1024
#define TS 256
#define K0T 1280
#define K1T 2048

typedef __half h16;

// ---------------- persistent device scratch ----------------
__device__ __align__(256) h16   g_W0[3ull * HH * K0T];
__device__ __align__(256) h16   g_W1[3ull * HH * K1T];
__device__ __align__(256) h16   g_Wfc[(size_t)DD * HH];
__device__ __align__(256) float g_C0[(size_t)BSz * 3 * HH];
__device__ __align__(256) float g_base1[3 * HH];
__device__ __align__(256) float g_h0[(size_t)BSz * HH];
__device__ __align__(256) float g_h1[(size_t)BSz * HH];
__device__ __align__(256) h16   g_A0[2][(size_t)BSz * K0T];
__device__ __align__(256) h16   g_A1[2][(size_t)BSz * K1T];
__device__ int g_fcdone[8];
__device__ int g_fccons[8];

// ---------------- helpers ----------------
__device__ __forceinline__ uint32_t smem_u32(const void* p) {
    return (uint32_t)__cvta_generic_to_shared(p);
}
__device__ __forceinline__ void cpa16(uint32_t d, const void* s) {
    asm volatile("cp.async.cg.shared.global [%0],[%1],16;" :: "r"(d), "l"(s));
}
#define CP_COMMIT() asm volatile("cp.async.commit_group;")
#define CP_WAIT1()  asm volatile("cp.async.wait_group 1;")
#define CP_WAIT0()  asm volatile("cp.async.wait_group 0;")

__device__ __forceinline__ void ldm4(uint32_t (&r)[4], uint32_t a) {
    asm volatile("ldmatrix.sync.aligned.m8n8.x4.shared.b16 {%0,%1,%2,%3},[%4];"
                 : "=r"(r[0]), "=r"(r[1]), "=r"(r[2]), "=r"(r[3]) : "r"(a));
}
__device__ __forceinline__ void ldm2(uint32_t (&r)[2], uint32_t a) {
    asm volatile("ldmatrix.sync.aligned.m8n8.x2.shared.b16 {%0,%1},[%2];"
                 : "=r"(r[0]), "=r"(r[1]) : "r"(a));
}
__device__ __forceinline__ void mma16(float (&c)[4], const uint32_t (&a)[4], uint32_t b0, uint32_t b1) {
    asm volatile("mma.sync.aligned.m16n8k16.row.col.f32.f16.f16.f32 "
                 "{%0,%1,%2,%3},{%4,%5,%6,%7},{%8,%9},{%0,%1,%2,%3};"
                 : "+f"(c[0]), "+f"(c[1]), "+f"(c[2]), "+f"(c[3])
                 : "r"(a[0]), "r"(a[1]), "r"(a[2]), "r"(a[3]), "r"(b0), "r"(b1));
}
__device__ __forceinline__ float fsigm(float x) { return __fdividef(1.f, 1.f + __expf(-x)); }

__device__ __forceinline__ uint32_t swz(int row, int sub) {
    return (uint32_t)(row * 128 + ((sub ^ (row & 7)) * 16));
}

// ---------------- GRU GEMM stage: K=64 chunk, warp tile 32x32 per gate ----------------
__device__ __forceinline__ void hstage(uint32_t st, float (&aR)[2][4][4], float (&aZ)[2][4][4],
                                       float (&aN)[2][4][4], int wm, int wn, int lane) {
#pragma unroll
    for (int kk = 0; kk < 4; kk++) {
        uint32_t af[2][4];
#pragma unroll
        for (int i = 0; i < 2; i++) {
            int r = wm * 32 + i * 16 + (lane & 15);
            ldm4(af[i], st + swz(r, 2 * kk + (lane >> 4)));
        }
        int nrow = wn * 32 + ((lane & 16) >> 1) + (lane & 7);
        int bch = 2 * kk + ((lane >> 3) & 1);
#pragma unroll
        for (int g = 0; g < 3; g++) {
            uint32_t sb = st + 16384 + g * 8192;
            float (&ac)[2][4][4] = (g == 0) ? aR : ((g == 1) ? aZ : aN);
#pragma unroll
            for (int j = 0; j < 2; j++) {
                uint32_t bf[4];
                ldm4(bf, sb + swz(nrow + j * 16, bch));
                mma16(ac[0][2 * j],     af[0], bf[0], bf[1]);
                mma16(ac[0][2 * j + 1], af[0], bf[2], bf[3]);
                mma16(ac[1][2 * j],     af[1], bf[0], bf[1]);
                mma16(ac[1][2 * j + 1], af[1], bf[2], bf[3]);
            }
        }
    }
}

// ---------------- FUSED kernel: gru0(t) on CTAs 0..127  +  fc(t-1) on CTAs 128..143 ----------------
__global__ void __launch_bounds__(256, 1) gru0f(int t, int dofc, const float* __restrict__ vghn,
                                                const float* __restrict__ bfc, float* __restrict__ out) {
    constexpr int NCH = K0T / 64;  // 20 ; x chunks 0..3, h0 chunks 4..19
    constexpr int STAGE = 40960;
    extern __shared__ char dsm[];
    const int tid = threadIdx.x, lane = tid & 31, warp = tid >> 5;
    const int idx = blockIdx.x;
    const uint32_t sbase = smem_u32(dsm);
    const int nt = (t + 1) & 1;

    if (idx < 128) {
        // ================== gru0 path (R4 layout, rotated chunk order) ==================
        const int wm = warp >> 1, wn = warp & 1;
        const int m0 = (idx >> 4) * 128, n0 = (idx & 15) * 64;
        const int mb = idx >> 4;
        const h16* A = g_A0[t & 1];

        auto load_chunk = [&](int c, int buf) {
            uint32_t st = sbase + buf * STAGE;
            int kb = c * 64;
#pragma unroll
            for (int l = 0; l < 10; l++) {
                int q = tid + l * 256;
                if (q < 1024) {
                    int row = q >> 3, sub = q & 7;
                    cpa16(st + swz(row, sub), A + (size_t)(m0 + row) * K0T + kb + sub * 8);
                } else {
                    int q2 = q - 1024;
                    int gate = q2 >> 9, r2 = q2 & 511;
                    int row = r2 >> 3, sub = r2 & 7;
                    cpa16(st + 16384 + gate * 8192 + swz(row, sub),
                          g_W0 + (size_t)gate * HH * K0T + (size_t)(n0 + row) * K0T + kb + sub * 8);
                }
            }
            CP_COMMIT();
        };

        float aR[2][4][4] = {}, aZ[2][4][4] = {}, aNi[2][4][4] = {}, aNh[2][4][4] = {};

        load_chunk(4, 0);                         // processing order: 4..19, then 0..3
#pragma unroll 1
        for (int i = 0; i < NCH; i++) {
            if (dofc && i == 15) {                // before loading first x chunk (i+1 = 16 -> c = 0)
                if (tid == 0) { while (atomicAdd(&g_fcdone[mb], 0) < 2) {} }
                __syncthreads();
                __threadfence();
                if (tid == 0) atomicAdd(&g_fccons[mb], 1);
            }
            if (i + 1 < NCH) { load_chunk((i + 5) % NCH, (i + 1) & 1); CP_WAIT1(); }
            else             { CP_WAIT0(); }
            __syncthreads();
            uint32_t st = sbase + (i & 1) * STAGE;
            int c = (i + 4) % NCH;
            if (c < 4) hstage(st, aR, aZ, aNi, wm, wn, lane);
            else       hstage(st, aR, aZ, aNh, wm, wn, lane);
            __syncthreads();
        }

        // flag reset (one CTA per m-block, after everyone consumed)
        if (dofc && (idx & 15) == 0 && tid == 0) {
            while (atomicAdd(&g_fccons[mb], 0) < 16) {}
            atomicExch(&g_fcdone[mb], 0);
            atomicExch(&g_fccons[mb], 0);
        }

        // ---- epilogue (R4 layer0) ----
        const int g4 = lane >> 2, t4 = lane & 3;
#pragma unroll
        for (int i = 0; i < 2; i++) {
            int rb = m0 + wm * 32 + i * 16 + g4;
#pragma unroll
            for (int j = 0; j < 4; j++) {
                int cc = n0 + wn * 32 + j * 8 + 2 * t4;
                float2 vg = *(const float2*)(vghn + cc);
#pragma unroll
                for (int hf = 0; hf < 2; hf++) {
                    int r = rb + hf * 8;
                    const float* cp = g_C0 + (size_t)r * 3072 + cc;
                    float2 cm_r = *(const float2*)cp;
                    float2 cm_z = *(const float2*)(cp + HH);
                    float2 cm_n = *(const float2*)(cp + 2 * HH);
                    float2 hp = *(const float2*)(g_h0 + (size_t)r * HH + cc);
                    float h[2];
#pragma unroll
                    for (int e = 0; e < 2; e++) {
                        float pr  = aR[i][j][hf * 2 + e]  + (e ? cm_r.y : cm_r.x);
                        float pz  = aZ[i][j][hf * 2 + e]  + (e ? cm_z.y : cm_z.x);
                        float gin = aNi[i][j][hf * 2 + e] + (e ? cm_n.y : cm_n.x);
                        float ghn = aNh[i][j][hf * 2 + e] + (e ? vg.y : vg.x);
                        float rr = fsigm(pr);
                        float zz = fsigm(pz);
                        float nn = tanhf(gin + rr * ghn);
                        float hv = e ? hp.y : hp.x;
                        h[e] = (1.f - zz) * nn + zz * hv;
                    }
                    *(float2*)(g_h0 + (size_t)r * HH + cc) = make_float2(h[0], h[1]);
                    __half2 hh = __floats2half2_rn(h[0], h[1]);
                    *(__half2*)(g_A1[t & 1] + (size_t)r * K1T + cc) = hh;
                    *(__half2*)(g_A0[nt] + (size_t)r * K0T + DD + cc) = hh;
                }
            }
        }
    } else {
        // ================== fc(t-1) path: CTA j = idx-128 handles rows j*64..j*64+63 ==================
        if (!dofc) return;
        const int j = idx - 128;
        const int m0f = j * 64;
        const int tp = t - 1;
        const int wm = warp >> 2, wn = warp & 3;
        const h16* Afc = g_A1[t & 1];      // h1n(t-1) at col offset HH
        h16* xdst = g_A0[t & 1];
        float* fsm = (float*)(dsm + 24576);

#pragma unroll 1
        for (int ntile = 0; ntile < 8; ntile++) {
            const int n0f = ntile * 32;
            auto ldc = [&](int c) {
                uint32_t st = sbase + (c & 1) * 12288;
                int kb = c * 64;
#pragma unroll
                for (int l = 0; l < 3; l++) {
                    int q = tid + l * 256;
                    if (q < 512) {
                        int row = q >> 3, sub = q & 7;
                        cpa16(st + swz(row, sub), Afc + (size_t)(m0f + row) * K1T + HH + kb + sub * 8);
                    } else {
                        int q2 = q - 512;
                        int row = q2 >> 3, sub = q2 & 7;
                        cpa16(st + 8192 + swz(row, sub), g_Wfc + (size_t)(n0f + row) * HH + kb + sub * 8);
                    }
                }
                CP_COMMIT();
            };
            float acc[2][4] = {};
            ldc(0);
#pragma unroll 1
            for (int c = 0; c < 16; c++) {
                if (c + 1 < 16) { ldc(c + 1); CP_WAIT1(); } else { CP_WAIT0(); }
                __syncthreads();
                uint32_t st = sbase + (c & 1) * 12288;
#pragma unroll
                for (int kk = 0; kk < 4; kk++) {
                    uint32_t af[2][4];
#pragma unroll
                    for (int i = 0; i < 2; i++) {
                        int r = wm * 32 + i * 16 + (lane & 15);
                        ldm4(af[i], st + swz(r, 2 * kk + (lane >> 4)));
                    }
                    int nrow = wn * 8 + (lane & 7);
                    int bch = 2 * kk + ((lane >> 3) & 1);
                    uint32_t bf[2];
                    ldm2(bf, st + 8192 + swz(nrow, bch));
                    mma16(acc[0], af[0], bf[0], bf[1]);
                    mma16(acc[1], af[1], bf[0], bf[1]);
                }
                __syncthreads();
            }
            // stage pre-activations (+bias)
            const int g4 = lane >> 2, t4 = lane & 3;
#pragma unroll
            for (int i = 0; i < 2; i++)
#pragma unroll
                for (int hf = 0; hf < 2; hf++) {
                    int r = wm * 32 + i * 16 + g4 + hf * 8;
                    int cl = wn * 8 + 2 * t4;
                    fsm[r * 34 + cl]     = acc[i][hf * 2]     + bfc[n0f + cl];
                    fsm[r * 34 + cl + 1] = acc[i][hf * 2 + 1] + bfc[n0f + cl + 1];
                }
            __syncthreads();
            if (n0f == 0) {
                if (tid < 64) {
                    int b = m0f + tid;
                    float* row = fsm + tid * 34;
                    float* op = out + (size_t)b * (TS * DD) + (size_t)tp * DD;
                    h16* xp = xdst + (size_t)b * K0T;
                    float mx = row[0];
                    for (int c = 1; c < 32; c++) mx = fmaxf(mx, row[c]);
                    float sum = 0.f;
                    for (int c = 0; c < 32; c++) { float e = __expf(row[c] - mx); row[c] = e; sum += e; }
                    float inv = __fdividef(1.f, sum);
                    for (int c = 0; c < 32; c++) { float v = row[c] * inv; op[c] = v; xp[c] = __float2half_rn(v); }
                }
            } else if (n0f == 32) {
                if (tid < 64) {
                    int b = m0f + tid;
                    float* row = fsm + tid * 34;
                    float* op = out + (size_t)b * (TS * DD) + (size_t)tp * DD + 32;
                    h16* xp = xdst + (size_t)b * K0T + 32;
                    float mx = row[0];
                    for (int c = 1; c < 15; c++) mx = fmaxf(mx, row[c]);
                    float sum = 0.f;
                    for (int c = 0; c < 15; c++) { float e = __expf(row[c] - mx); row[c] = e; sum += e; }
                    float inv = __fdividef(1.f, sum);
                    for (int c = 0; c < 15; c++) { float v = row[c] * inv; op[c] = v; xp[c] = __float2half_rn(v); }
                    for (int c = 15; c < 32; c++) { float v = fsigm(row[c]); op[c] = v; xp[c] = __float2half_rn(v); }
                }
            } else {
                for (int q = tid; q < 2048; q += 256) {
                    int r = q >> 5, cl = q & 31;
                    int b = m0f + r, c = n0f + cl;
                    float v = fsigm(fsm[r * 34 + cl]);
                    out[(size_t)b * (TS * DD) + (size_t)tp * DD + c] = v;
                    xdst[(size_t)b * K0T + c] = __float2half_rn(v);
                }
            }
            __syncthreads();
        }
        __threadfence();
        __syncthreads();
        if (tid == 0) atomicAdd(&g_fcdone[j >> 1], 1);
    }
}

// ---------------- gru1 kernel (exact R4) ----------------
template <int KT, int KX>
__global__ void __launch_bounds__(256, 1) gru_hmma(int t, const float* __restrict__ vghn) {
    constexpr int NCH = KT / 64;
    constexpr int STAGE = 40960;
    extern __shared__ char dsm[];
    const int tid = threadIdx.x, lane = tid & 31, warp = tid >> 5;
    const int wm = warp >> 1, wn = warp & 1;
    const int m0 = blockIdx.y * 128, n0 = blockIdx.x * 64;
    const uint32_t sbase = smem_u32(dsm);
    const h16* A = g_A1[t & 1];

    auto load_chunk = [&](int c) {
        uint32_t st = sbase + (c & 1) * STAGE;
        int kb = c * 64;
#pragma unroll
        for (int l = 0; l < 10; l++) {
            int q = tid + l * 256;
            if (q < 1024) {
                int row = q >> 3, sub = q & 7;
                cpa16(st + swz(row, sub), A + (size_t)(m0 + row) * KT + kb + sub * 8);
            } else {
                int q2 = q - 1024;
                int gate = q2 >> 9, r2 = q2 & 511;
                int row = r2 >> 3, sub = r2 & 7;
                cpa16(st + 16384 + gate * 8192 + swz(row, sub),
                      g_W1 + (size_t)gate * HH * KT + (size_t)(n0 + row) * KT + kb + sub * 8);
            }
        }
        CP_COMMIT();
    };

    float aR[2][4][4] = {}, aZ[2][4][4] = {}, aNi[2][4][4] = {}, aNh[2][4][4] = {};

    load_chunk(0);
#pragma unroll 1
    for (int c = 0; c < NCH; c++) {
        if (c + 1 < NCH) { load_chunk(c + 1); CP_WAIT1(); }
        else             { CP_WAIT0(); }
        __syncthreads();
        uint32_t st = sbase + (c & 1) * STAGE;
        if (c * 64 < KX) hstage(st, aR, aZ, aNi, wm, wn, lane);
        else             hstage(st, aR, aZ, aNh, wm, wn, lane);
        __syncthreads();
    }

    const int nt = (t + 1) & 1;
    const int g4 = lane >> 2, t4 = lane & 3;
#pragma unroll
    for (int i = 0; i < 2; i++) {
        int rb = m0 + wm * 32 + i * 16 + g4;
#pragma unroll
        for (int j = 0; j < 4; j++) {
            int cc = n0 + wn * 32 + j * 8 + 2 * t4;
            float2 v1r = *(const float2*)(g_base1 + cc);
            float2 v1z = *(const float2*)(g_base1 + HH + cc);
            float2 v1n = *(const float2*)(g_base1 + 2 * HH + cc);
            float2 vg = *(const float2*)(vghn + cc);
#pragma unroll
            for (int hf = 0; hf < 2; hf++) {
                int r = rb + hf * 8;
                float2 hp = *(const float2*)(g_h1 + (size_t)r * HH + cc);
                float h[2];
#pragma unroll
                for (int e = 0; e < 2; e++) {
                    float pr  = aR[i][j][hf * 2 + e]  + (e ? v1r.y : v1r.x);
                    float pz  = aZ[i][j][hf * 2 + e]  + (e ? v1z.y : v1z.x);
                    float gin = aNi[i][j][hf * 2 + e] + (e ? v1n.y : v1n.x);
                    float ghn = aNh[i][j][hf * 2 + e] + (e ? vg.y : vg.x);
                    float rr = fsigm(pr);
                    float zz = fsigm(pz);
                    float nn = tanhf(gin + rr * ghn);
                    float hv = e ? hp.y : hp.x;
                    h[e] = (1.f - zz) * nn + zz * hv;
                }
                *(float2*)(g_h1 + (size_t)r * HH + cc) = make_float2(h[0], h[1]);
                __half2 hh = __floats2half2_rn(h[0], h[1]);
                *(__half2*)(g_A1[nt] + (size_t)r * K1T + HH + cc) = hh;
            }
        }
    }
}

// ---------------- trailing FC (exact R4 fc, used once for t=255) ----------------
__global__ void __launch_bounds__(256, 1) fc_hmma(int t, const float* __restrict__ bfc, float* __restrict__ out) {
    constexpr int STAGE = 12288;
    extern __shared__ char dsm[];
    const int tid = threadIdx.x, lane = tid & 31, warp = tid >> 5;
    const int wm = warp >> 2, wn = warp & 3;
    const int m0 = blockIdx.y * 64, n0 = blockIdx.x * 32;
    const int nt = (t + 1) & 1;
    const uint32_t sbase = smem_u32(dsm);
    const h16* A = g_A1[nt];

    auto load_chunk = [&](int c) {
        uint32_t st = sbase + (c & 1) * STAGE;
        int kb = c * 64;
#pragma unroll
        for (int l = 0; l < 3; l++) {
            int q = tid + l * 256;
            if (q < 512) {
                int row = q >> 3, sub = q & 7;
                cpa16(st + swz(row, sub), A + (size_t)(m0 + row) * K1T + HH + kb + sub * 8);
            } else {
                int q2 = q - 512;
                int row = q2 >> 3, sub = q2 & 7;
                cpa16(st + 8192 + swz(row, sub), g_Wfc + (size_t)(n0 + row) * HH + kb + sub * 8);
            }
        }
        CP_COMMIT();
    };

    float acc[2][4] = {};
    load_chunk(0);
#pragma unroll 1
    for (int c = 0; c < 16; c++) {
        if (c + 1 < 16) { load_chunk(c + 1); CP_WAIT1(); } else { CP_WAIT0(); }
        __syncthreads();
        uint32_t st = sbase + (c & 1) * STAGE;
#pragma unroll
        for (int kk = 0; kk < 4; kk++) {
            uint32_t af[2][4];
#pragma unroll
            for (int i = 0; i < 2; i++) {
                int r = wm * 32 + i * 16 + (lane & 15);
                ldm4(af[i], st + swz(r, 2 * kk + (lane >> 4)));
            }
            int nrow = wn * 8 + (lane & 7);
            int bch = 2 * kk + ((lane >> 3) & 1);
            uint32_t bf[2];
            ldm2(bf, st + 8192 + swz(nrow, bch));
            mma16(acc[0], af[0], bf[0], bf[1]);
            mma16(acc[1], af[1], bf[0], bf[1]);
        }
        __syncthreads();
    }

    float* fsm = (float*)dsm;
    const int g4 = lane >> 2, t4 = lane & 3;
#pragma unroll
    for (int i = 0; i < 2; i++)
#pragma unroll
        for (int hf = 0; hf < 2; hf++) {
            int r = wm * 32 + i * 16 + g4 + hf * 8;
            int cl = wn * 8 + 2 * t4;
            fsm[r * 34 + cl]     = acc[i][hf * 2]     + bfc[n0 + cl];
            fsm[r * 34 + cl + 1] = acc[i][hf * 2 + 1] + bfc[n0 + cl + 1];
        }
    __syncthreads();

    const int bx = blockIdx.x;
    if (bx == 0) {
        if (tid < 64) {
            int b = m0 + tid;
            float* row = fsm + tid * 34;
            float* op = out + (size_t)b * (TS * DD) + (size_t)t * DD;
            h16* xp = g_A0[nt] + (size_t)b * K0T;
            float mx = row[0];
            for (int c = 1; c < 32; c++) mx = fmaxf(mx, row[c]);
            float sum = 0.f;
            for (int c = 0; c < 32; c++) { float e = __expf(row[c] - mx); row[c] = e; sum += e; }
            float inv = __fdividef(1.f, sum);
            for (int c = 0; c < 32; c++) { float v = row[c] * inv; op[c] = v; xp[c] = __float2half_rn(v); }
        }
    } else if (bx == 1) {
        if (tid < 64) {
            int b = m0 + tid;
            float* row = fsm + tid * 34;
            float* op = out + (size_t)b * (TS * DD) + (size_t)t * DD + 32;
            h16* xp = g_A0[nt] + (size_t)b * K0T + 32;
            float mx = row[0];
            for (int c = 1; c < 15; c++) mx = fmaxf(mx, row[c]);
            float sum = 0.f;
            for (int c = 0; c < 15; c++) { float e = __expf(row[c] - mx); row[c] = e; sum += e; }
            float inv = __fdividef(1.f, sum);
            for (int c = 0; c < 15; c++) { float v = row[c] * inv; op[c] = v; xp[c] = __float2half_rn(v); }
            for (int c = 15; c < 32; c++) { float v = fsigm(row[c]); op[c] = v; xp[c] = __float2half_rn(v); }
        }
    } else {
        for (int idx = tid; idx < 2048; idx += 256) {
            int r = idx >> 5, cl = idx & 31;
            int b = m0 + r, c = n0 + cl;
            float v = fsigm(fsm[r * 34 + cl]);
            out[(size_t)b * (TS * DD) + (size_t)t * DD + c] = v;
            g_A0[nt][(size_t)b * K0T + c] = __float2half_rn(v);
        }
    }
}

// ---------------- C0 (fp32, once per replay) ----------------
__global__ void __launch_bounds__(256) c0_kernel(const float* __restrict__ emb, const float* __restrict__ Wih0,
                                                 const float* __restrict__ bih0, const float* __restrict__ bhh0) {
    __shared__ float As[16][64], Bs[16][64];
    int tid = threadIdx.x;
    int tx = tid & 15, ty = tid >> 4;
    int m0 = blockIdx.y * 64, n0 = blockIdx.x * 64;
    float acc[4][4] = {};
    for (int k0 = 0; k0 < HH; k0 += 16) {
#pragma unroll
        for (int l = 0; l < 4; l++) {
            int e = tid + l * 256;
            int rr = e >> 4, kk = e & 15;
            As[kk][rr] = emb[(size_t)(m0 + rr) * 3072 + k0 + kk];
            Bs[kk][rr] = Wih0[(size_t)(n0 + rr) * K0T + k0 + kk];
        }
        __syncthreads();
#pragma unroll
        for (int kk = 0; kk < 16; kk++) {
            float av[4], bv[4];
#pragma unroll
            for (int i = 0; i < 4; i++) av[i] = As[kk][ty * 4 + i];
#pragma unroll
            for (int j = 0; j < 4; j++) bv[j] = Bs[kk][tx * 4 + j];
#pragma unroll
            for (int i = 0; i < 4; i++)
#pragma unroll
                for (int j = 0; j < 4; j++) acc[i][j] += av[i] * bv[j];
        }
        __syncthreads();
    }
#pragma unroll
    for (int i = 0; i < 4; i++)
#pragma unroll
        for (int j = 0; j < 4; j++) {
            int r = m0 + ty * 4 + i, c = n0 + tx * 4 + j;
            g_C0[(size_t)r * 3072 + c] = acc[i][j] + bih0[c] + (c < 2 * HH ? bhh0[c] : 0.f);
        }
}

// ---------------- combined setup ----------------
__global__ void setup_all(const float* __restrict__ Wih0, const float* __restrict__ Whh0,
                          const float* __restrict__ Wih1, const float* __restrict__ Whh1,
                          const float* __restrict__ Wfc,  const float* __restrict__ bih1,
                          const float* __restrict__ bhh1, const float* __restrict__ emb,
                          const float* __restrict__ dyn) {
    const int stride = gridDim.x * blockDim.x;
    const int t0 = blockIdx.x * blockDim.x + threadIdx.x;
    for (int idx = t0; idx < 3 * HH * K0T; idx += stride) {
        int gr = idx / K0T, k = idx - gr * K0T;
        float v = (k < DD) ? Wih0[(size_t)gr * K0T + HH + k] : Whh0[(size_t)gr * HH + (k - DD)];
        g_W0[idx] = __float2half_rn(v);
    }
    for (int idx = t0; idx < 3 * HH * K1T; idx += stride) {
        int gr = idx / K1T, k = idx - gr * K1T;
        float v = (k < HH) ? Wih1[(size_t)gr * HH + k] : Whh1[(size_t)gr * HH + (k - HH)];
        g_W1[idx] = __float2half_rn(v);
    }
    for (int i = t0; i < DD * HH; i += stride) {
        g_Wfc[i] = __float2half_rn(Wfc[i]);
        if (i < 3 * HH) g_base1[i] = bih1[i] + (i < 2 * HH ? bhh1[i] : 0.f);
    }
    for (int i = t0; i < BSz * HH; i += stride) {
        int b = i >> 10, n = i & 1023;
        float h0 = emb[(size_t)b * 3072 + HH + n];
        float h1 = emb[(size_t)b * 3072 + 2 * HH + n];
        g_h0[i] = h0;
        g_h1[i] = h1;
        g_A0[0][(size_t)b * K0T + DD + n] = __float2half_rn(h0);
        g_A1[0][(size_t)b * K1T + HH + n] = __float2half_rn(h1);
        if (n < DD) g_A0[0][(size_t)b * K0T + n] = __float2half_rn(dyn[(size_t)b * TS * DD + n]);
    }
    if (t0 < 8) { g_fcdone[t0] = 0; g_fccons[t0] = 0; }
}

// ---------------- host ----------------
extern "C" void kernel_launch(void* const* d_in, const int* in_sizes, int n_in,
                              void* d_out, int out_size) {
    const float* emb  = (const float*)d_in[0];
    const float* dyn  = (const float*)d_in[1];
    const float* Wih0 = (const float*)d_in[3];
    const float* Whh0 = (const float*)d_in[4];
    const float* bih0 = (const float*)d_in[5];
    const float* bhh0 = (const float*)d_in[6];
    const float* Wih1 = (const float*)d_in[7];
    const float* Whh1 = (const float*)d_in[8];
    const float* bih1 = (const float*)d_in[9];
    const float* bhh1 = (const float*)d_in[10];
    const float* Wfc  = (const float*)d_in[11];
    const float* bfc  = (const float*)d_in[12];
    float* out = (float*)d_out;

    const int SM = 2 * 40960;  // 81920 bytes
    cudaFuncSetAttribute((const void*)gru0f, cudaFuncAttributeMaxDynamicSharedMemorySize, SM);
    cudaFuncSetAttribute((const void*)gru_hmma<K1T, HH>, cudaFuncAttributeMaxDynamicSharedMemorySize, SM);
    const int SMF = 2 * 12288;
    cudaFuncSetAttribute((const void*)fc_hmma, cudaFuncAttributeMaxDynamicSharedMemorySize, SMF);

    setup_all<<<2048, 256>>>(Wih0, Whh0, Wih1, Whh1, Wfc, bih1, bhh1, emb, dyn);
    c0_kernel<<<dim3(48, 16), 256>>>(emb, Wih0, bih0, bhh0);

    for (int t = 0; t < TS; t++) {
        gru0f<<<144, 256, SM>>>(t, t > 0 ? 1 : 0, bhh0 + 2 * HH, bfc, out);
        gru_hmma<K1T, HH><<<dim3(16, 8), 256, SM>>>(t, bhh1 + 2 * HH);
    }
    fc_hmma<<<dim3(8, 16), 256, SMF>>>(255, bfc, out);
}

// round 16
// speedup vs baseline: 2.2131x; 1.2489x over previous
#include <cuda_runtime.h>
#include <cuda_fp16.h>
#include <cstdint>
#include <cstddef>

#define HH 1024
#define DD 256
#define BSz 1024
#define TS 256
#define K0T 1280
#define K1T 2048

typedef __half h16;

// ---------------- persistent device scratch ----------------
__device__ __align__(256) h16   g_W0[3ull * HH * K0T];
__device__ __align__(256) h16   g_W1[3ull * HH * K1T];
__device__ __align__(256) h16   g_Wfc[(size_t)DD * HH];
__device__ __align__(256) float g_C0[(size_t)BSz * 3 * HH];
__device__ __align__(256) float g_base1[3 * HH];
__device__ __align__(256) float g_h0[(size_t)BSz * HH];
__device__ __align__(256) float g_h1[(size_t)BSz * HH];
__device__ __align__(256) h16   g_A0[2][(size_t)BSz * K0T];
__device__ __align__(256) h16   g_A1[2][(size_t)BSz * K1T];
__device__ int g_fcdone;
__device__ int g_fccons;

// ---------------- helpers ----------------
__device__ __forceinline__ uint32_t smem_u32(const void* p) {
    return (uint32_t)__cvta_generic_to_shared(p);
}
__device__ __forceinline__ void cpa16(uint32_t d, const void* s) {
    asm volatile("cp.async.cg.shared.global [%0],[%1],16;" :: "r"(d), "l"(s));
}
#define CP_COMMIT() asm volatile("cp.async.commit_group;")
#define CP_WAIT1()  asm volatile("cp.async.wait_group 1;")
#define CP_WAIT0()  asm volatile("cp.async.wait_group 0;")

__device__ __forceinline__ void ldm4(uint32_t (&r)[4], uint32_t a) {
    asm volatile("ldmatrix.sync.aligned.m8n8.x4.shared.b16 {%0,%1,%2,%3},[%4];"
                 : "=r"(r[0]), "=r"(r[1]), "=r"(r[2]), "=r"(r[3]) : "r"(a));
}
__device__ __forceinline__ void ldm2(uint32_t (&r)[2], uint32_t a) {
    asm volatile("ldmatrix.sync.aligned.m8n8.x2.shared.b16 {%0,%1},[%2];"
                 : "=r"(r[0]), "=r"(r[1]) : "r"(a));
}
__device__ __forceinline__ void mma16(float (&c)[4], const uint32_t (&a)[4], uint32_t b0, uint32_t b1) {
    asm volatile("mma.sync.aligned.m16n8k16.row.col.f32.f16.f16.f32 "
                 "{%0,%1,%2,%3},{%4,%5,%6,%7},{%8,%9},{%0,%1,%2,%3};"
                 : "+f"(c[0]), "+f"(c[1]), "+f"(c[2]), "+f"(c[3])
                 : "r"(a[0]), "r"(a[1]), "r"(a[2]), "r"(a[3]), "r"(b0), "r"(b1));
}
__device__ __forceinline__ float fsigm(float x) { return __fdividef(1.f, 1.f + __expf(-x)); }

__device__ __forceinline__ uint32_t swz(int row, int sub) {
    return (uint32_t)(row * 128 + ((sub ^ (row & 7)) * 16));
}

// ---------------- GRU GEMM stage: K=64 chunk, warp tile 32x32 per gate ----------------
__device__ __forceinline__ void hstage(uint32_t st, float (&aR)[2][4][4], float (&aZ)[2][4][4],
                                       float (&aN)[2][4][4], int wm, int wn, int lane) {
#pragma unroll
    for (int kk = 0; kk < 4; kk++) {
        uint32_t af[2][4];
#pragma unroll
        for (int i = 0; i < 2; i++) {
            int r = wm * 32 + i * 16 + (lane & 15);
            ldm4(af[i], st + swz(r, 2 * kk + (lane >> 4)));
        }
        int nrow = wn * 32 + ((lane & 16) >> 1) + (lane & 7);
        int bch = 2 * kk + ((lane >> 3) & 1);
#pragma unroll
        for (int g = 0; g < 3; g++) {
            uint32_t sb = st + 16384 + g * 8192;
            float (&ac)[2][4][4] = (g == 0) ? aR : ((g == 1) ? aZ : aN);
#pragma unroll
            for (int j = 0; j < 2; j++) {
                uint32_t bf[4];
                ldm4(bf, sb + swz(nrow + j * 16, bch));
                mma16(ac[0][2 * j],     af[0], bf[0], bf[1]);
                mma16(ac[0][2 * j + 1], af[0], bf[2], bf[3]);
                mma16(ac[1][2 * j],     af[1], bf[0], bf[1]);
                mma16(ac[1][2 * j + 1], af[1], bf[2], bf[3]);
            }
        }
    }
}

// ---------------- FUSED kernel: fc(t-1) prologue (1 tile/CTA) + gru0(t) ----------------
__global__ void __launch_bounds__(256, 1) gru0f(int t, int dofc, const float* __restrict__ vghn,
                                                const float* __restrict__ bfc, float* __restrict__ out) {
    constexpr int NCH = K0T / 64;  // 20; x chunks 0..3, h0 chunks 4..19
    constexpr int STAGE = 40960;
    extern __shared__ char dsm[];
    const int tid = threadIdx.x, lane = tid & 31, warp = tid >> 5;
    const int idx = blockIdx.x;
    const uint32_t sbase = smem_u32(dsm);
    const int nt = (t + 1) & 1;

    // ========== fc(t-1) prologue: CTA idx -> tile (m = idx&15 of 64 rows, n = idx>>4 of 32 cols) ==========
    if (dofc) {
        const int m0f = (idx & 15) * 64;
        const int bx = idx >> 4;
        const int n0f = bx * 32;
        const int tp = t - 1;
        const int fwm = warp >> 2, fwn = warp & 3;
        const h16* Afc = g_A1[t & 1];         // h1n(t-1) at col offset HH
        h16* xdst = g_A0[t & 1];
        float* fsm = (float*)(dsm + 24576);

        auto ldc = [&](int c) {
            uint32_t st = sbase + (c & 1) * 12288;
            int kb = c * 64;
#pragma unroll
            for (int l = 0; l < 3; l++) {
                int q = tid + l * 256;
                if (q < 512) {
                    int row = q >> 3, sub = q & 7;
                    cpa16(st + swz(row, sub), Afc + (size_t)(m0f + row) * K1T + HH + kb + sub * 8);
                } else {
                    int q2 = q - 512;
                    int row = q2 >> 3, sub = q2 & 7;
                    cpa16(st + 8192 + swz(row, sub), g_Wfc + (size_t)(n0f + row) * HH + kb + sub * 8);
                }
            }
            CP_COMMIT();
        };

        float acc[2][4] = {};
        ldc(0);
#pragma unroll 1
        for (int c = 0; c < 16; c++) {
            if (c + 1 < 16) { ldc(c + 1); CP_WAIT1(); } else { CP_WAIT0(); }
            __syncthreads();
            uint32_t st = sbase + (c & 1) * 12288;
#pragma unroll
            for (int kk = 0; kk < 4; kk++) {
                uint32_t af[2][4];
#pragma unroll
                for (int i = 0; i < 2; i++) {
                    int r = fwm * 32 + i * 16 + (lane & 15);
                    ldm4(af[i], st + swz(r, 2 * kk + (lane >> 4)));
                }
                int nrow = fwn * 8 + (lane & 7);
                int bch = 2 * kk + ((lane >> 3) & 1);
                uint32_t bf[2];
                ldm2(bf, st + 8192 + swz(nrow, bch));
                mma16(acc[0], af[0], bf[0], bf[1]);
                mma16(acc[1], af[1], bf[0], bf[1]);
            }
            __syncthreads();
        }
        const int g4 = lane >> 2, t4 = lane & 3;
#pragma unroll
        for (int i = 0; i < 2; i++)
#pragma unroll
            for (int hf = 0; hf < 2; hf++) {
                int r = fwm * 32 + i * 16 + g4 + hf * 8;
                int cl = fwn * 8 + 2 * t4;
                fsm[r * 34 + cl]     = acc[i][hf * 2]     + bfc[n0f + cl];
                fsm[r * 34 + cl + 1] = acc[i][hf * 2 + 1] + bfc[n0f + cl + 1];
            }
        __syncthreads();
        if (bx == 0) {
            if (tid < 64) {
                int b = m0f + tid;
                float* row = fsm + tid * 34;
                float* op = out + (size_t)b * (TS * DD) + (size_t)tp * DD;
                h16* xp = xdst + (size_t)b * K0T;
                float mx = row[0];
                for (int c = 1; c < 32; c++) mx = fmaxf(mx, row[c]);
                float sum = 0.f;
                for (int c = 0; c < 32; c++) { float e = __expf(row[c] - mx); row[c] = e; sum += e; }
                float inv = __fdividef(1.f, sum);
                for (int c = 0; c < 32; c++) { float v = row[c] * inv; op[c] = v; xp[c] = __float2half_rn(v); }
            }
        } else if (bx == 1) {
            if (tid < 64) {
                int b = m0f + tid;
                float* row = fsm + tid * 34;
                float* op = out + (size_t)b * (TS * DD) + (size_t)tp * DD + 32;
                h16* xp = xdst + (size_t)b * K0T + 32;
                float mx = row[0];
                for (int c = 1; c < 15; c++) mx = fmaxf(mx, row[c]);
                float sum = 0.f;
                for (int c = 0; c < 15; c++) { float e = __expf(row[c] - mx); row[c] = e; sum += e; }
                float inv = __fdividef(1.f, sum);
                for (int c = 0; c < 15; c++) { float v = row[c] * inv; op[c] = v; xp[c] = __float2half_rn(v); }
                for (int c = 15; c < 32; c++) { float v = fsigm(row[c]); op[c] = v; xp[c] = __float2half_rn(v); }
            }
        } else {
            for (int q = tid; q < 2048; q += 256) {
                int r = q >> 5, cl = q & 31;
                int b = m0f + r, c = n0f + cl;
                float v = fsigm(fsm[r * 34 + cl]);
                out[(size_t)b * (TS * DD) + (size_t)tp * DD + c] = v;
                xdst[(size_t)b * K0T + c] = __float2half_rn(v);
            }
        }
        __threadfence();
        __syncthreads();
        if (tid == 0) atomicAdd(&g_fcdone, 1);
    }

    // ========== gru0(t): R4 layout, rotated chunk order (h0 chunks first) ==========
    const int wm = warp >> 1, wn = warp & 1;
    const int m0 = (idx >> 4) * 128, n0 = (idx & 15) * 64;
    const h16* A = g_A0[t & 1];

    auto load_chunk = [&](int c, int buf) {
        uint32_t st = sbase + buf * STAGE;
        int kb = c * 64;
#pragma unroll
        for (int l = 0; l < 10; l++) {
            int q = tid + l * 256;
            if (q < 1024) {
                int row = q >> 3, sub = q & 7;
                cpa16(st + swz(row, sub), A + (size_t)(m0 + row) * K0T + kb + sub * 8);
            } else {
                int q2 = q - 1024;
                int gate = q2 >> 9, r2 = q2 & 511;
                int row = r2 >> 3, sub = r2 & 7;
                cpa16(st + 16384 + gate * 8192 + swz(row, sub),
                      g_W0 + (size_t)gate * HH * K0T + (size_t)(n0 + row) * K0T + kb + sub * 8);
            }
        }
        CP_COMMIT();
    };

    float aR[2][4][4] = {}, aZ[2][4][4] = {}, aNi[2][4][4] = {}, aNh[2][4][4] = {};

    load_chunk(4, 0);   // order: 4..19 then 0..3
#pragma unroll 1
    for (int i = 0; i < NCH; i++) {
        if (dofc && i == 15) {       // next load is chunk (16+4)%20 = 0 -> needs fc outputs
            if (tid == 0) {
                while (atomicAdd(&g_fcdone, 0) < 128) {}
                atomicAdd(&g_fccons, 1);
            }
            __syncthreads();
            __threadfence();
        }
        if (i + 1 < NCH) { load_chunk((i + 5) % NCH, (i + 1) & 1); CP_WAIT1(); }
        else             { CP_WAIT0(); }
        __syncthreads();
        uint32_t st = sbase + (i & 1) * STAGE;
        int c = (i + 4) % NCH;
        if (c < 4) hstage(st, aR, aZ, aNi, wm, wn, lane);
        else       hstage(st, aR, aZ, aNh, wm, wn, lane);
        __syncthreads();
    }

    // ---- epilogue (R4 layer0) ----
    const int g4 = lane >> 2, t4 = lane & 3;
#pragma unroll
    for (int i = 0; i < 2; i++) {
        int rb = m0 + wm * 32 + i * 16 + g4;
#pragma unroll
        for (int j = 0; j < 4; j++) {
            int cc = n0 + wn * 32 + j * 8 + 2 * t4;
            float2 vg = *(const float2*)(vghn + cc);
#pragma unroll
            for (int hf = 0; hf < 2; hf++) {
                int r = rb + hf * 8;
                const float* cp = g_C0 + (size_t)r * 3072 + cc;
                float2 cm_r = *(const float2*)cp;
                float2 cm_z = *(const float2*)(cp + HH);
                float2 cm_n = *(const float2*)(cp + 2 * HH);
                float2 hp = *(const float2*)(g_h0 + (size_t)r * HH + cc);
                float h[2];
#pragma unroll
                for (int e = 0; e < 2; e++) {
                    float pr  = aR[i][j][hf * 2 + e]  + (e ? cm_r.y : cm_r.x);
                    float pz  = aZ[i][j][hf * 2 + e]  + (e ? cm_z.y : cm_z.x);
                    float gin = aNi[i][j][hf * 2 + e] + (e ? cm_n.y : cm_n.x);
                    float ghn = aNh[i][j][hf * 2 + e] + (e ? vg.y : vg.x);
                    float rr = fsigm(pr);
                    float zz = fsigm(pz);
                    float nn = tanhf(gin + rr * ghn);
                    float hv = e ? hp.y : hp.x;
                    h[e] = (1.f - zz) * nn + zz * hv;
                }
                *(float2*)(g_h0 + (size_t)r * HH + cc) = make_float2(h[0], h[1]);
                __half2 hh = __floats2half2_rn(h[0], h[1]);
                *(__half2*)(g_A1[t & 1] + (size_t)r * K1T + cc) = hh;
                *(__half2*)(g_A0[nt] + (size_t)r * K0T + DD + cc) = hh;
            }
        }
    }

    // ---- flag reset (single CTA, after all consumed) ----
    if (dofc && idx == 0 && tid == 0) {
        while (atomicAdd(&g_fccons, 0) < 128) {}
        atomicExch(&g_fcdone, 0);
        atomicExch(&g_fccons, 0);
    }
}

// ---------------- gru1 kernel (exact R4) ----------------
__global__ void __launch_bounds__(256, 1) gru1k(int t, const float* __restrict__ vghn) {
    constexpr int NCH = K1T / 64;
    constexpr int STAGE = 40960;
    extern __shared__ char dsm[];
    const int tid = threadIdx.x, lane = tid & 31, warp = tid >> 5;
    const int wm = warp >> 1, wn = warp & 1;
    const int m0 = blockIdx.y * 128, n0 = blockIdx.x * 64;
    const uint32_t sbase = smem_u32(dsm);
    const h16* A = g_A1[t & 1];

    auto load_chunk = [&](int c) {
        uint32_t st = sbase + (c & 1) * STAGE;
        int kb = c * 64;
#pragma unroll
        for (int l = 0; l < 10; l++) {
            int q = tid + l * 256;
            if (q < 1024) {
                int row = q >> 3, sub = q & 7;
                cpa16(st + swz(row, sub), A + (size_t)(m0 + row) * K1T + kb + sub * 8);
            } else {
                int q2 = q - 1024;
                int gate = q2 >> 9, r2 = q2 & 511;
                int row = r2 >> 3, sub = r2 & 7;
                cpa16(st + 16384 + gate * 8192 + swz(row, sub),
                      g_W1 + (size_t)gate * HH * K1T + (size_t)(n0 + row) * K1T + kb + sub * 8);
            }
        }
        CP_COMMIT();
    };

    float aR[2][4][4] = {}, aZ[2][4][4] = {}, aNi[2][4][4] = {}, aNh[2][4][4] = {};

    load_chunk(0);
#pragma unroll 1
    for (int c = 0; c < NCH; c++) {
        if (c + 1 < NCH) { load_chunk(c + 1); CP_WAIT1(); }
        else             { CP_WAIT0(); }
        __syncthreads();
        uint32_t st = sbase + (c & 1) * STAGE;
        if (c < 16) hstage(st, aR, aZ, aNi, wm, wn, lane);
        else        hstage(st, aR, aZ, aNh, wm, wn, lane);
        __syncthreads();
    }

    const int nt = (t + 1) & 1;
    const int g4 = lane >> 2, t4 = lane & 3;
#pragma unroll
    for (int i = 0; i < 2; i++) {
        int rb = m0 + wm * 32 + i * 16 + g4;
#pragma unroll
        for (int j = 0; j < 4; j++) {
            int cc = n0 + wn * 32 + j * 8 + 2 * t4;
            float2 v1r = *(const float2*)(g_base1 + cc);
            float2 v1z = *(const float2*)(g_base1 + HH + cc);
            float2 v1n = *(const float2*)(g_base1 + 2 * HH + cc);
            float2 vg = *(const float2*)(vghn + cc);
#pragma unroll
            for (int hf = 0; hf < 2; hf++) {
                int r = rb + hf * 8;
                float2 hp = *(const float2*)(g_h1 + (size_t)r * HH + cc);
                float h[2];
#pragma unroll
                for (int e = 0; e < 2; e++) {
                    float pr  = aR[i][j][hf * 2 + e]  + (e ? v1r.y : v1r.x);
                    float pz  = aZ[i][j][hf * 2 + e]  + (e ? v1z.y : v1z.x);
                    float gin = aNi[i][j][hf * 2 + e] + (e ? v1n.y : v1n.x);
                    float ghn = aNh[i][j][hf * 2 + e] + (e ? vg.y : vg.x);
                    float rr = fsigm(pr);
                    float zz = fsigm(pz);
                    float nn = tanhf(gin + rr * ghn);
                    float hv = e ? hp.y : hp.x;
                    h[e] = (1.f - zz) * nn + zz * hv;
                }
                *(float2*)(g_h1 + (size_t)r * HH + cc) = make_float2(h[0], h[1]);
                __half2 hh = __floats2half2_rn(h[0], h[1]);
                *(__half2*)(g_A1[nt] + (size_t)r * K1T + HH + cc) = hh;
            }
        }
    }
}

// ---------------- trailing FC (exact R4 fc, t=255 only) ----------------
__global__ void __launch_bounds__(256, 1) fc_hmma(int t, const float* __restrict__ bfc, float* __restrict__ out) {
    extern __shared__ char dsm[];
    const int tid = threadIdx.x, lane = tid & 31, warp = tid >> 5;
    const int wm = warp >> 2, wn = warp & 3;
    const int m0 = blockIdx.y * 64, n0 = blockIdx.x * 32;
    const int nt = (t + 1) & 1;
    const uint32_t sbase = smem_u32(dsm);
    const h16* A = g_A1[nt];

    auto load_chunk = [&](int c) {
        uint32_t st = sbase + (c & 1) * 12288;
        int kb = c * 64;
#pragma unroll
        for (int l = 0; l < 3; l++) {
            int q = tid + l * 256;
            if (q < 512) {
                int row = q >> 3, sub = q & 7;
                cpa16(st + swz(row, sub), A + (size_t)(m0 + row) * K1T + HH + kb + sub * 8);
            } else {
                int q2 = q - 512;
                int row = q2 >> 3, sub = q2 & 7;
                cpa16(st + 8192 + swz(row, sub), g_Wfc + (size_t)(n0 + row) * HH + kb + sub * 8);
            }
        }
        CP_COMMIT();
    };

    float acc[2][4] = {};
    load_chunk(0);
#pragma unroll 1
    for (int c = 0; c < 16; c++) {
        if (c + 1 < 16) { load_chunk(c + 1); CP_WAIT1(); } else { CP_WAIT0(); }
        __syncthreads();
        uint32_t st = sbase + (c & 1) * 12288;
#pragma unroll
        for (int kk = 0; kk < 4; kk++) {
            uint32_t af[2][4];
#pragma unroll
            for (int i = 0; i < 2; i++) {
                int r = wm * 32 + i * 16 + (lane & 15);
                ldm4(af[i], st + swz(r, 2 * kk + (lane >> 4)));
            }
            int nrow = wn * 8 + (lane & 7);
            int bch = 2 * kk + ((lane >> 3) & 1);
            uint32_t bf[2];
            ldm2(bf, st + 8192 + swz(nrow, bch));
            mma16(acc[0], af[0], bf[0], bf[1]);
            mma16(acc[1], af[1], bf[0], bf[1]);
        }
        __syncthreads();
    }

    float* fsm = (float*)dsm;
    const int g4 = lane >> 2, t4 = lane & 3;
#pragma unroll
    for (int i = 0; i < 2; i++)
#pragma unroll
        for (int hf = 0; hf < 2; hf++) {
            int r = wm * 32 + i * 16 + g4 + hf * 8;
            int cl = wn * 8 + 2 * t4;
            fsm[r * 34 + cl]     = acc[i][hf * 2]     + bfc[n0 + cl];
            fsm[r * 34 + cl + 1] = acc[i][hf * 2 + 1] + bfc[n0 + cl + 1];
        }
    __syncthreads();

    const int bx = blockIdx.x;
    if (bx == 0) {
        if (tid < 64) {
            int b = m0 + tid;
            float* row = fsm + tid * 34;
            float* op = out + (size_t)b * (TS * DD) + (size_t)t * DD;
            float mx = row[0];
            for (int c = 1; c < 32; c++) mx = fmaxf(mx, row[c]);
            float sum = 0.f;
            for (int c = 0; c < 32; c++) { float e = __expf(row[c] - mx); row[c] = e; sum += e; }
            float inv = __fdividef(1.f, sum);
            for (int c = 0; c < 32; c++) op[c] = row[c] * inv;
        }
    } else if (bx == 1) {
        if (tid < 64) {
            int b = m0 + tid;
            float* row = fsm + tid * 34;
            float* op = out + (size_t)b * (TS * DD) + (size_t)t * DD + 32;
            float mx = row[0];
            for (int c = 1; c < 15; c++) mx = fmaxf(mx, row[c]);
            float sum = 0.f;
            for (int c = 0; c < 15; c++) { float e = __expf(row[c] - mx); row[c] = e; sum += e; }
            float inv = __fdividef(1.f, sum);
            for (int c = 0; c < 15; c++) op[c] = row[c] * inv;
            for (int c = 15; c < 32; c++) op[c] = fsigm(row[c]);
        }
    } else {
        for (int idx = tid; idx < 2048; idx += 256) {
            int r = idx >> 5, cl = idx & 31;
            int b = m0 + r, c = n0 + cl;
            out[(size_t)b * (TS * DD) + (size_t)t * DD + c] = fsigm(fsm[r * 34 + cl]);
        }
    }
}

// ---------------- C0 (fp32, once per replay) ----------------
__global__ void __launch_bounds__(256) c0_kernel(const float* __restrict__ emb, const float* __restrict__ Wih0,
                                                 const float* __restrict__ bih0, const float* __restrict__ bhh0) {
    __shared__ float As[16][64], Bs[16][64];
    int tid = threadIdx.x;
    int tx = tid & 15, ty = tid >> 4;
    int m0 = blockIdx.y * 64, n0 = blockIdx.x * 64;
    float acc[4][4] = {};
    for (int k0 = 0; k0 < HH; k0 += 16) {
#pragma unroll
        for (int l = 0; l < 4; l++) {
            int e = tid + l * 256;
            int rr = e >> 4, kk = e & 15;
            As[kk][rr] = emb[(size_t)(m0 + rr) * 3072 + k0 + kk];
            Bs[kk][rr] = Wih0[(size_t)(n0 + rr) * K0T + k0 + kk];
        }
        __syncthreads();
#pragma unroll
        for (int kk = 0; kk < 16; kk++) {
            float av[4], bv[4];
#pragma unroll
            for (int i = 0; i < 4; i++) av[i] = As[kk][ty * 4 + i];
#pragma unroll
            for (int j = 0; j < 4; j++) bv[j] = Bs[kk][tx * 4 + j];
#pragma unroll
            for (int i = 0; i < 4; i++)
#pragma unroll
                for (int j = 0; j < 4; j++) acc[i][j] += av[i] * bv[j];
        }
        __syncthreads();
    }
#pragma unroll
    for (int i = 0; i < 4; i++)
#pragma unroll
        for (int j = 0; j < 4; j++) {
            int r = m0 + ty * 4 + i, c = n0 + tx * 4 + j;
            g_C0[(size_t)r * 3072 + c] = acc[i][j] + bih0[c] + (c < 2 * HH ? bhh0[c] : 0.f);
        }
}

// ---------------- combined setup ----------------
__global__ void setup_all(const float* __restrict__ Wih0, const float* __restrict__ Whh0,
                          const float* __restrict__ Wih1, const float* __restrict__ Whh1,
                          const float* __restrict__ Wfc,  const float* __restrict__ bih1,
                          const float* __restrict__ bhh1, const float* __restrict__ emb,
                          const float* __restrict__ dyn) {
    const int stride = gridDim.x * blockDim.x;
    const int t0 = blockIdx.x * blockDim.x + threadIdx.x;
    for (int idx = t0; idx < 3 * HH * K0T; idx += stride) {
        int gr = idx / K0T, k = idx - gr * K0T;
        float v = (k < DD) ? Wih0[(size_t)gr * K0T + HH + k] : Whh0[(size_t)gr * HH + (k - DD)];
        g_W0[idx] = __float2half_rn(v);
    }
    for (int idx = t0; idx < 3 * HH * K1T; idx += stride) {
        int gr = idx / K1T, k = idx - gr * K1T;
        float v = (k < HH) ? Wih1[(size_t)gr * HH + k] : Whh1[(size_t)gr * HH + (k - HH)];
        g_W1[idx] = __float2half_rn(v);
    }
    for (int i = t0; i < DD * HH; i += stride) {
        g_Wfc[i] = __float2half_rn(Wfc[i]);
        if (i < 3 * HH) g_base1[i] = bih1[i] + (i < 2 * HH ? bhh1[i] : 0.f);
    }
    for (int i = t0; i < BSz * HH; i += stride) {
        int b = i >> 10, n = i & 1023;
        float h0 = emb[(size_t)b * 3072 + HH + n];
        float h1 = emb[(size_t)b * 3072 + 2 * HH + n];
        g_h0[i] = h0;
        g_h1[i] = h1;
        g_A0[0][(size_t)b * K0T + DD + n] = __float2half_rn(h0);
        g_A1[0][(size_t)b * K1T + HH + n] = __float2half_rn(h1);
        if (n < DD) g_A0[0][(size_t)b * K0T + n] = __float2half_rn(dyn[(size_t)b * TS * DD + n]);
    }
    if (t0 == 0) { g_fcdone = 0; g_fccons = 0; }
}

// ---------------- host ----------------
extern "C" void kernel_launch(void* const* d_in, const int* in_sizes, int n_in,
                              void* d_out, int out_size) {
    const float* emb  = (const float*)d_in[0];
    const float* dyn  = (const float*)d_in[1];
    const float* Wih0 = (const float*)d_in[3];
    const float* Whh0 = (const float*)d_in[4];
    const float* bih0 = (const float*)d_in[5];
    const float* bhh0 = (const float*)d_in[6];
    const float* Wih1 = (const float*)d_in[7];
    const float* Whh1 = (const float*)d_in[8];
    const float* bih1 = (const float*)d_in[9];
    const float* bhh1 = (const float*)d_in[10];
    const float* Wfc  = (const float*)d_in[11];
    const float* bfc  = (const float*)d_in[12];
    float* out = (float*)d_out;

    const int SM = 2 * 40960;  // 81920 bytes
    cudaFuncSetAttribute((const void*)gru0f, cudaFuncAttributeMaxDynamicSharedMemorySize, SM);
    cudaFuncSetAttribute((const void*)gru1k, cudaFuncAttributeMaxDynamicSharedMemorySize, SM);
    const int SMF = 2 * 12288;
    cudaFuncSetAttribute((const void*)fc_hmma, cudaFuncAttributeMaxDynamicSharedMemorySize, SMF);

    setup_all<<<2048, 256>>>(Wih0, Whh0, Wih1, Whh1, Wfc, bih1, bhh1, emb, dyn);
    c0_kernel<<<dim3(48, 16), 256>>>(emb, Wih0, bih0, bhh0);

    for (int t = 0; t < TS; t++) {
        gru0f<<<128, 256, SM>>>(t, t > 0 ? 1 : 0, bhh0 + 2 * HH, bfc, out);
        gru1k<<<dim3(16, 8), 256, SM>>>(t, bhh1 + 2 * HH);
    }
    fc_hmma<<<dim3(8, 16), 256, SMF>>>(255, bfc, out);
}